// round 1
// baseline (speedup 1.0000x reference)
#include <cuda_runtime.h>
#include <math.h>

#define NN 24000
#define EE 96000
#define BB 1200
#define NPG 20

// ---------------- device scratch (no allocations allowed) ----------------
__device__ float g_q1[NN*512];
__device__ float g_k1[NN*512];
__device__ float g_v1[NN*512];
__device__ float g_s1[NN*512];
__device__ float g_h1[NN*512];
__device__ float g_q2[NN*1024];
__device__ float g_k2[NN*1024];
__device__ float g_v2[NN*1024];
__device__ float g_s2[NN*1024];
__device__ float g_h2[NN*1024];
__device__ float g_concat[BB*1280];
__device__ int   g_deg[NN];
__device__ int   g_offs[NN+1];
__device__ int   g_cursor[NN];
__device__ int   g_eidx[EE];

// ---------------- CSR build ----------------
__global__ void zero_deg_kernel() {
    int i = blockIdx.x*blockDim.x + threadIdx.x;
    if (i < NN) g_deg[i] = 0;
}

__global__ void hist_kernel(const int* __restrict__ dst) {
    int e = blockIdx.x*blockDim.x + threadIdx.x;
    if (e < EE) atomicAdd(&g_deg[dst[e]], 1);
}

// single-block exclusive scan of g_deg -> g_offs (and g_cursor copy)
__global__ void scan_kernel() {
    __shared__ int wsum[32];
    __shared__ int carry;
    int tid = threadIdx.x;
    int lane = tid & 31, wid = tid >> 5;
    if (tid == 0) carry = 0;
    __syncthreads();
    for (int base = 0; base < NN; base += 1024) {
        int i = base + tid;
        int v = (i < NN) ? g_deg[i] : 0;
        int x = v;
        #pragma unroll
        for (int o = 1; o < 32; o <<= 1) {
            int y = __shfl_up_sync(0xffffffffu, x, o);
            if (lane >= o) x += y;
        }
        if (lane == 31) wsum[wid] = x;
        __syncthreads();
        if (wid == 0) {
            int s = wsum[lane];
            #pragma unroll
            for (int o = 1; o < 32; o <<= 1) {
                int y = __shfl_up_sync(0xffffffffu, s, o);
                if (lane >= o) s += y;
            }
            wsum[lane] = s;
        }
        __syncthreads();
        int pre = (wid > 0 ? wsum[wid-1] : 0) + carry;
        int incl = x + pre;
        if (i < NN) { g_offs[i] = incl - v; g_cursor[i] = incl - v; }
        __syncthreads();
        if (tid == 1023) carry = incl;
        __syncthreads();
    }
    if (tid == 0) g_offs[NN] = carry;
}

__global__ void scatter_kernel(const int* __restrict__ dst) {
    int e = blockIdx.x*blockDim.x + threadIdx.x;
    if (e < EE) {
        int p = atomicAdd(&g_cursor[dst[e]], 1);
        g_eidx[p] = e;
    }
}

// deterministic order: sort each node's small edge list ascending (deg ~ 4)
__global__ void sort_kernel() {
    int n = blockIdx.x*blockDim.x + threadIdx.x;
    if (n >= NN) return;
    int a = g_offs[n], b = g_offs[n+1];
    for (int i = a+1; i < b; ++i) {
        int key = g_eidx[i];
        int j = i-1;
        while (j >= a && g_eidx[j] > key) { g_eidx[j+1] = g_eidx[j]; --j; }
        g_eidx[j+1] = key;
    }
}

// ---------------- layer-1 projections: x[N,9] -> q1,k1,v1,s1 [N,512] ----------------
__global__ void proj1_kernel(const float* __restrict__ x,
    const float* __restrict__ Wq, const float* __restrict__ bq,
    const float* __restrict__ Wk, const float* __restrict__ bk,
    const float* __restrict__ Wv, const float* __restrict__ bv,
    const float* __restrict__ Ws, const float* __restrict__ bs)
{
    int warp = (blockIdx.x*blockDim.x + threadIdx.x) >> 5;
    int lane = threadIdx.x & 31;
    if (warp >= NN) return;
    float xr[9];
    #pragma unroll
    for (int t = 0; t < 9; ++t) xr[t] = __ldg(&x[warp*9 + t]);
    for (int j = lane; j < 512; j += 32) {
        float aq = __ldg(&bq[j]), ak = __ldg(&bk[j]);
        float av = __ldg(&bv[j]), as_ = __ldg(&bs[j]);
        #pragma unroll
        for (int t = 0; t < 9; ++t) {
            float xv = xr[t];
            aq  = fmaf(xv, __ldg(&Wq[t*512+j]), aq);
            ak  = fmaf(xv, __ldg(&Wk[t*512+j]), ak);
            av  = fmaf(xv, __ldg(&Wv[t*512+j]), av);
            as_ = fmaf(xv, __ldg(&Ws[t*512+j]), as_);
        }
        size_t o = (size_t)warp*512 + j;
        g_q1[o] = aq; g_k1[o] = ak; g_v1[o] = av; g_s1[o] = as_;
    }
}

// ---------------- attention: one warp per destination node, online softmax ----------------
// Channel layout: lane l owns channels [l*VPT, (l+1)*VPT); head = lane/8.
// Edge features e = edge_attr @ We computed inline from smem (transposed [c][4] layout).
template<int D, int H, bool RELU>
__global__ void __launch_bounds__(256) attn_kernel(
    const float* __restrict__ q, const float* __restrict__ k,
    const float* __restrict__ v, const float* __restrict__ s,
    const float* __restrict__ ea, const float* __restrict__ We,
    const int* __restrict__ srcArr, float* __restrict__ out)
{
    constexpr int VPT = D / 32;
    constexpr int NV4 = VPT / 4;
    constexpr int C = D / H;
    __shared__ float sWeT[4*D];   // sWeT[c*4 + t] = We[t*D + c]
    for (int i = threadIdx.x; i < 4*D; i += blockDim.x) {
        int c = i >> 2, t = i & 3;
        sWeT[i] = __ldg(&We[t*D + c]);
    }
    __syncthreads();

    int warp = (blockIdx.x*blockDim.x + threadIdx.x) >> 5;
    int lane = threadIdx.x & 31;
    if (warp >= NN) return;
    int cbase = lane * VPT;

    float4 qr[NV4], acc[NV4];
    const float4* q4 = (const float4*)(q + (size_t)warp*D + cbase);
    #pragma unroll
    for (int i = 0; i < NV4; ++i) { qr[i] = __ldg(q4 + i); acc[i] = make_float4(0.f,0.f,0.f,0.f); }

    float m = -INFINITY, den = 0.f;
    const float invs = rsqrtf((float)C);
    const float4* sWe4 = (const float4*)sWeT;

    int e0 = g_offs[warp], e1 = g_offs[warp+1];
    for (int t = e0; t < e1; ++t) {
        int e  = __ldg(&g_eidx[t]);
        int sn = __ldg(&srcArr[e]);
        float4 a4 = __ldg((const float4*)ea + e);
        const float4* k4 = (const float4*)(k + (size_t)sn*D + cbase);
        float p = 0.f;
        #pragma unroll
        for (int i = 0; i < NV4; ++i) {
            float4 kk = __ldg(k4 + i);
            int c = cbase + 4*i;
            float4 w0 = sWe4[c+0], w1 = sWe4[c+1], w2 = sWe4[c+2], w3 = sWe4[c+3];
            float ex0 = a4.x*w0.x + a4.y*w0.y + a4.z*w0.z + a4.w*w0.w;
            float ex1 = a4.x*w1.x + a4.y*w1.y + a4.z*w1.z + a4.w*w1.w;
            float ex2 = a4.x*w2.x + a4.y*w2.y + a4.z*w2.z + a4.w*w2.w;
            float ex3 = a4.x*w3.x + a4.y*w3.y + a4.z*w3.z + a4.w*w3.w;
            p += qr[i].x*(kk.x+ex0) + qr[i].y*(kk.y+ex1)
               + qr[i].z*(kk.z+ex2) + qr[i].w*(kk.w+ex3);
        }
        // reduce across the 8 lanes of this head
        p += __shfl_xor_sync(0xffffffffu, p, 1);
        p += __shfl_xor_sync(0xffffffffu, p, 2);
        p += __shfl_xor_sync(0xffffffffu, p, 4);
        float alpha = p * invs;
        float nm = fmaxf(m, alpha);
        float sc = __expf(m - nm);       // first edge: exp(-inf) = 0
        float w  = __expf(alpha - nm);
        den = den*sc + w;
        m = nm;
        const float4* v4 = (const float4*)(v + (size_t)sn*D + cbase);
        #pragma unroll
        for (int i = 0; i < NV4; ++i) {
            float4 vv = __ldg(v4 + i);
            int c = cbase + 4*i;
            float4 w0 = sWe4[c+0], w1 = sWe4[c+1], w2 = sWe4[c+2], w3 = sWe4[c+3];
            float ex0 = a4.x*w0.x + a4.y*w0.y + a4.z*w0.z + a4.w*w0.w;
            float ex1 = a4.x*w1.x + a4.y*w1.y + a4.z*w1.z + a4.w*w1.w;
            float ex2 = a4.x*w2.x + a4.y*w2.y + a4.z*w2.z + a4.w*w2.w;
            float ex3 = a4.x*w3.x + a4.y*w3.y + a4.z*w3.z + a4.w*w3.w;
            acc[i].x = acc[i].x*sc + w*(vv.x+ex0);
            acc[i].y = acc[i].y*sc + w*(vv.y+ex1);
            acc[i].z = acc[i].z*sc + w*(vv.z+ex2);
            acc[i].w = acc[i].w*sc + w*(vv.w+ex3);
        }
    }
    float r = 1.f / (den + 1e-16f);
    const float4* s4 = (const float4*)(s + (size_t)warp*D + cbase);
    float4* o4 = (float4*)(out + (size_t)warp*D + cbase);
    #pragma unroll
    for (int i = 0; i < NV4; ++i) {
        float4 sv = __ldg(s4 + i);
        float4 o;
        o.x = acc[i].x*r + sv.x;
        o.y = acc[i].y*r + sv.y;
        o.z = acc[i].z*r + sv.z;
        o.w = acc[i].w*r + sv.w;
        if (RELU) {
            o.x = fmaxf(o.x, 0.f); o.y = fmaxf(o.y, 0.f);
            o.z = fmaxf(o.z, 0.f); o.w = fmaxf(o.w, 0.f);
        }
        o4[i] = o;
    }
}

// ---------------- fp32 tiled GEMM: C[M,N] = A[M,K] @ B[K,N] + bias ----------------
// BM=128, BN=64, BK=16, 256 threads, 8x4 per thread.
__global__ void __launch_bounds__(256) gemm_kernel(
    const float* __restrict__ A, const float* __restrict__ Bm,
    const float* __restrict__ bias, float* __restrict__ C,
    int M, int N, int K, int ldc, int coff)
{
    __shared__ float As[16][128+4];
    __shared__ float Bs[16][64+4];
    int tid = threadIdx.x;
    int tx = tid & 15, ty = tid >> 4;
    int m0 = blockIdx.x * 128;
    int n0 = blockIdx.y * 64;
    float acc[8][4] = {};

    for (int k0 = 0; k0 < K; k0 += 16) {
        #pragma unroll
        for (int it = 0; it < 2; ++it) {
            int f = tid + it*256;
            int row = f >> 2;
            int c4 = (f & 3) * 4;
            float4 val = make_float4(0.f,0.f,0.f,0.f);
            if (m0 + row < M)
                val = __ldg((const float4*)&A[(size_t)(m0+row)*K + k0 + c4]);
            As[c4+0][row] = val.x; As[c4+1][row] = val.y;
            As[c4+2][row] = val.z; As[c4+3][row] = val.w;
        }
        {
            int r  = tid >> 4;
            int c4 = (tid & 15) * 4;
            float4 val = __ldg((const float4*)&Bm[(size_t)(k0+r)*N + n0 + c4]);
            *(float4*)&Bs[r][c4] = val;
        }
        __syncthreads();
        #pragma unroll
        for (int kk = 0; kk < 16; ++kk) {
            float a[8], b[4];
            *(float4*)&a[0] = *(const float4*)&As[kk][ty*8];
            *(float4*)&a[4] = *(const float4*)&As[kk][ty*8+4];
            *(float4*)&b[0] = *(const float4*)&Bs[kk][tx*4];
            #pragma unroll
            for (int i = 0; i < 8; ++i)
                #pragma unroll
                for (int j = 0; j < 4; ++j)
                    acc[i][j] = fmaf(a[i], b[j], acc[i][j]);
        }
        __syncthreads();
    }
    #pragma unroll
    for (int i = 0; i < 8; ++i) {
        int row = m0 + ty*8 + i;
        if (row < M) {
            #pragma unroll
            for (int j = 0; j < 4; ++j) {
                int col = n0 + tx*4 + j;
                C[(size_t)row*ldc + coff + col] = acc[i][j] + __ldg(&bias[col]);
            }
        }
    }
}

// ---------------- mean pool over 20 nodes per graph -> concat[:, :1024] ----------------
__global__ void pool_kernel() {
    int c = blockIdx.y*blockDim.x + threadIdx.x;   // 0..1023
    int b = blockIdx.x;
    float sum = 0.f;
    #pragma unroll
    for (int i = 0; i < NPG; ++i)
        sum += g_h2[(size_t)(b*NPG + i)*1024 + c];
    g_concat[b*1280 + c] = sum * (1.f/NPG);
}

// ---------------- launch ----------------
extern "C" void kernel_launch(void* const* d_in, const int* in_sizes, int n_in,
                              void* d_out, int out_size)
{
    const float* x    = (const float*)d_in[0];
    const int*   ei   = (const int*)  d_in[1];
    const float* ea   = (const float*)d_in[2];
    const float* fpb  = (const float*)d_in[4];
    const float *Wq1=(const float*)d_in[5],  *bq1=(const float*)d_in[6];
    const float *Wk1=(const float*)d_in[7],  *bk1=(const float*)d_in[8];
    const float *Wv1=(const float*)d_in[9],  *bv1=(const float*)d_in[10];
    const float *We1=(const float*)d_in[11];
    const float *Ws1=(const float*)d_in[12], *bs1=(const float*)d_in[13];
    const float *Wq2=(const float*)d_in[14], *bq2=(const float*)d_in[15];
    const float *Wk2=(const float*)d_in[16], *bk2=(const float*)d_in[17];
    const float *Wv2=(const float*)d_in[18], *bv2=(const float*)d_in[19];
    const float *We2=(const float*)d_in[20];
    const float *Ws2=(const float*)d_in[21], *bs2=(const float*)d_in[22];
    const float *Wfp=(const float*)d_in[23], *bfp=(const float*)d_in[24];
    const float *Wfin=(const float*)d_in[25],*bfin=(const float*)d_in[26];

    const int* srcArr = ei;
    const int* dstArr = ei + EE;

    float *q1,*k1,*v1,*s1,*h1,*q2,*k2,*v2,*s2,*h2,*cc;
    cudaGetSymbolAddress((void**)&q1, g_q1);
    cudaGetSymbolAddress((void**)&k1, g_k1);
    cudaGetSymbolAddress((void**)&v1, g_v1);
    cudaGetSymbolAddress((void**)&s1, g_s1);
    cudaGetSymbolAddress((void**)&h1, g_h1);
    cudaGetSymbolAddress((void**)&q2, g_q2);
    cudaGetSymbolAddress((void**)&k2, g_k2);
    cudaGetSymbolAddress((void**)&v2, g_v2);
    cudaGetSymbolAddress((void**)&s2, g_s2);
    cudaGetSymbolAddress((void**)&h2, g_h2);
    cudaGetSymbolAddress((void**)&cc, g_concat);

    // CSR build (reused by both layers)
    zero_deg_kernel<<<(NN+255)/256, 256>>>();
    hist_kernel<<<(EE+255)/256, 256>>>(dstArr);
    scan_kernel<<<1, 1024>>>();
    scatter_kernel<<<(EE+255)/256, 256>>>(dstArr);
    sort_kernel<<<(NN+255)/256, 256>>>();

    // layer 1
    proj1_kernel<<<(NN*32+255)/256, 256>>>(x, Wq1,bq1, Wk1,bk1, Wv1,bv1, Ws1,bs1);
    attn_kernel<512,4,true><<<(NN*32+255)/256, 256>>>(q1,k1,v1,s1, ea, We1, srcArr, h1);

    // layer 2 projections (the FLOP hotspot)
    dim3 g2((NN+127)/128, 1024/64);
    gemm_kernel<<<g2, 256>>>(h1, Wq2, bq2, q2, NN, 1024, 512, 1024, 0);
    gemm_kernel<<<g2, 256>>>(h1, Wk2, bk2, k2, NN, 1024, 512, 1024, 0);
    gemm_kernel<<<g2, 256>>>(h1, Wv2, bv2, v2, NN, 1024, 512, 1024, 0);
    gemm_kernel<<<g2, 256>>>(h1, Ws2, bs2, s2, NN, 1024, 512, 1024, 0);

    attn_kernel<1024,4,false><<<(NN*32+255)/256, 256>>>(q2,k2,v2,s2, ea, We2, srcArr, h2);

    // pooling + fingerprint + final
    pool_kernel<<<dim3(BB, 4), 256>>>();
    gemm_kernel<<<dim3((BB+127)/128, 256/64), 256>>>(fpb, Wfp, bfp, cc, BB, 256, 2048, 1280, 1024);
    gemm_kernel<<<dim3((BB+127)/128, 1024/64), 256>>>(cc, Wfin, bfin, (float*)d_out, BB, 1024, 1280, 1024, 0);
}

// round 2
// speedup vs baseline: 1.7279x; 1.7279x over previous
#include <cuda_runtime.h>
#include <math.h>
#include <stdint.h>

#define NN 24000
#define EE 96000
#define BB 1200
#define NPG 20

// ---------------- device scratch (no allocations allowed) ----------------
__device__ float g_q1[NN*512];
__device__ float g_k1[NN*512];
__device__ float g_v1[NN*512];
__device__ float g_s1[NN*512];
__device__ float g_h1[NN*512];
__device__ float g_q2[NN*1024];
__device__ float g_k2[NN*1024];
__device__ float g_v2[NN*1024];
__device__ float g_s2[NN*1024];
__device__ float g_h2[NN*1024];
__device__ float g_concat[BB*1280];
__device__ int   g_deg[NN];
__device__ int   g_offs[NN+1];
__device__ int   g_cursor[NN];
__device__ int   g_eidx[EE];

// ---------------- CSR build ----------------
__global__ void zero_deg_kernel() {
    int i = blockIdx.x*blockDim.x + threadIdx.x;
    if (i < NN) g_deg[i] = 0;
}

__global__ void hist_kernel(const int* __restrict__ dst) {
    int e = blockIdx.x*blockDim.x + threadIdx.x;
    if (e < EE) atomicAdd(&g_deg[dst[e]], 1);
}

// single-block exclusive scan of g_deg -> g_offs (and g_cursor copy)
__global__ void scan_kernel() {
    __shared__ int wsum[32];
    __shared__ int carry;
    int tid = threadIdx.x;
    int lane = tid & 31, wid = tid >> 5;
    if (tid == 0) carry = 0;
    __syncthreads();
    for (int base = 0; base < NN; base += 1024) {
        int i = base + tid;
        int v = (i < NN) ? g_deg[i] : 0;
        int x = v;
        #pragma unroll
        for (int o = 1; o < 32; o <<= 1) {
            int y = __shfl_up_sync(0xffffffffu, x, o);
            if (lane >= o) x += y;
        }
        if (lane == 31) wsum[wid] = x;
        __syncthreads();
        if (wid == 0) {
            int s = wsum[lane];
            #pragma unroll
            for (int o = 1; o < 32; o <<= 1) {
                int y = __shfl_up_sync(0xffffffffu, s, o);
                if (lane >= o) s += y;
            }
            wsum[lane] = s;
        }
        __syncthreads();
        int pre = (wid > 0 ? wsum[wid-1] : 0) + carry;
        int incl = x + pre;
        if (i < NN) { g_offs[i] = incl - v; g_cursor[i] = incl - v; }
        __syncthreads();
        if (tid == 1023) carry = incl;
        __syncthreads();
    }
    if (tid == 0) g_offs[NN] = carry;
}

__global__ void scatter_kernel(const int* __restrict__ dst) {
    int e = blockIdx.x*blockDim.x + threadIdx.x;
    if (e < EE) {
        int p = atomicAdd(&g_cursor[dst[e]], 1);
        g_eidx[p] = e;
    }
}

// deterministic order: sort each node's small edge list ascending (deg ~ 4)
__global__ void sort_kernel() {
    int n = blockIdx.x*blockDim.x + threadIdx.x;
    if (n >= NN) return;
    int a = g_offs[n], b = g_offs[n+1];
    for (int i = a+1; i < b; ++i) {
        int key = g_eidx[i];
        int j = i-1;
        while (j >= a && g_eidx[j] > key) { g_eidx[j+1] = g_eidx[j]; --j; }
        g_eidx[j+1] = key;
    }
}

// ---------------- layer-1 projections: x[N,9] -> q1,k1,v1,s1 [N,512] ----------------
__global__ void proj1_kernel(const float* __restrict__ x,
    const float* __restrict__ Wq, const float* __restrict__ bq,
    const float* __restrict__ Wk, const float* __restrict__ bk,
    const float* __restrict__ Wv, const float* __restrict__ bv,
    const float* __restrict__ Ws, const float* __restrict__ bs)
{
    int warp = (blockIdx.x*blockDim.x + threadIdx.x) >> 5;
    int lane = threadIdx.x & 31;
    if (warp >= NN) return;
    float xr[9];
    #pragma unroll
    for (int t = 0; t < 9; ++t) xr[t] = __ldg(&x[warp*9 + t]);
    for (int j = lane; j < 512; j += 32) {
        float aq = __ldg(&bq[j]), ak = __ldg(&bk[j]);
        float av = __ldg(&bv[j]), as_ = __ldg(&bs[j]);
        #pragma unroll
        for (int t = 0; t < 9; ++t) {
            float xv = xr[t];
            aq  = fmaf(xv, __ldg(&Wq[t*512+j]), aq);
            ak  = fmaf(xv, __ldg(&Wk[t*512+j]), ak);
            av  = fmaf(xv, __ldg(&Wv[t*512+j]), av);
            as_ = fmaf(xv, __ldg(&Ws[t*512+j]), as_);
        }
        size_t o = (size_t)warp*512 + j;
        g_q1[o] = aq; g_k1[o] = ak; g_v1[o] = av; g_s1[o] = as_;
    }
}

// ---------------- attention: one warp per destination node, online softmax ----------------
template<int D, int H, bool RELU>
__global__ void __launch_bounds__(256) attn_kernel(
    const float* __restrict__ q, const float* __restrict__ k,
    const float* __restrict__ v, const float* __restrict__ s,
    const float* __restrict__ ea, const float* __restrict__ We,
    const int* __restrict__ srcArr, float* __restrict__ out)
{
    constexpr int VPT = D / 32;
    constexpr int NV4 = VPT / 4;
    constexpr int C = D / H;
    __shared__ float sWeT[4*D];   // sWeT[c*4 + t] = We[t*D + c]
    for (int i = threadIdx.x; i < 4*D; i += blockDim.x) {
        int c = i >> 2, t = i & 3;
        sWeT[i] = __ldg(&We[t*D + c]);
    }
    __syncthreads();

    int warp = (blockIdx.x*blockDim.x + threadIdx.x) >> 5;
    int lane = threadIdx.x & 31;
    if (warp >= NN) return;
    int cbase = lane * VPT;

    float4 qr[NV4], acc[NV4];
    const float4* q4 = (const float4*)(q + (size_t)warp*D + cbase);
    #pragma unroll
    for (int i = 0; i < NV4; ++i) { qr[i] = __ldg(q4 + i); acc[i] = make_float4(0.f,0.f,0.f,0.f); }

    float m = -INFINITY, den = 0.f;
    const float invs = rsqrtf((float)C);
    const float4* sWe4 = (const float4*)sWeT;

    int e0 = g_offs[warp], e1 = g_offs[warp+1];
    for (int t = e0; t < e1; ++t) {
        int e  = __ldg(&g_eidx[t]);
        int sn = __ldg(&srcArr[e]);
        float4 a4 = __ldg((const float4*)ea + e);
        const float4* k4 = (const float4*)(k + (size_t)sn*D + cbase);
        float p = 0.f;
        #pragma unroll
        for (int i = 0; i < NV4; ++i) {
            float4 kk = __ldg(k4 + i);
            int c = cbase + 4*i;
            float4 w0 = sWe4[c+0], w1 = sWe4[c+1], w2 = sWe4[c+2], w3 = sWe4[c+3];
            float ex0 = a4.x*w0.x + a4.y*w0.y + a4.z*w0.z + a4.w*w0.w;
            float ex1 = a4.x*w1.x + a4.y*w1.y + a4.z*w1.z + a4.w*w1.w;
            float ex2 = a4.x*w2.x + a4.y*w2.y + a4.z*w2.z + a4.w*w2.w;
            float ex3 = a4.x*w3.x + a4.y*w3.y + a4.z*w3.z + a4.w*w3.w;
            p += qr[i].x*(kk.x+ex0) + qr[i].y*(kk.y+ex1)
               + qr[i].z*(kk.z+ex2) + qr[i].w*(kk.w+ex3);
        }
        p += __shfl_xor_sync(0xffffffffu, p, 1);
        p += __shfl_xor_sync(0xffffffffu, p, 2);
        p += __shfl_xor_sync(0xffffffffu, p, 4);
        float alpha = p * invs;
        float nm = fmaxf(m, alpha);
        float sc = __expf(m - nm);
        float w  = __expf(alpha - nm);
        den = den*sc + w;
        m = nm;
        const float4* v4 = (const float4*)(v + (size_t)sn*D + cbase);
        #pragma unroll
        for (int i = 0; i < NV4; ++i) {
            float4 vv = __ldg(v4 + i);
            int c = cbase + 4*i;
            float4 w0 = sWe4[c+0], w1 = sWe4[c+1], w2 = sWe4[c+2], w3 = sWe4[c+3];
            float ex0 = a4.x*w0.x + a4.y*w0.y + a4.z*w0.z + a4.w*w0.w;
            float ex1 = a4.x*w1.x + a4.y*w1.y + a4.z*w1.z + a4.w*w1.w;
            float ex2 = a4.x*w2.x + a4.y*w2.y + a4.z*w2.z + a4.w*w2.w;
            float ex3 = a4.x*w3.x + a4.y*w3.y + a4.z*w3.z + a4.w*w3.w;
            acc[i].x = acc[i].x*sc + w*(vv.x+ex0);
            acc[i].y = acc[i].y*sc + w*(vv.y+ex1);
            acc[i].z = acc[i].z*sc + w*(vv.z+ex2);
            acc[i].w = acc[i].w*sc + w*(vv.w+ex3);
        }
    }
    float r = 1.f / (den + 1e-16f);
    const float4* s4 = (const float4*)(s + (size_t)warp*D + cbase);
    float4* o4 = (float4*)(out + (size_t)warp*D + cbase);
    #pragma unroll
    for (int i = 0; i < NV4; ++i) {
        float4 sv = __ldg(s4 + i);
        float4 o;
        o.x = acc[i].x*r + sv.x;
        o.y = acc[i].y*r + sv.y;
        o.z = acc[i].z*r + sv.z;
        o.w = acc[i].w*r + sv.w;
        if (RELU) {
            o.x = fmaxf(o.x, 0.f); o.y = fmaxf(o.y, 0.f);
            o.z = fmaxf(o.z, 0.f); o.w = fmaxf(o.w, 0.f);
        }
        o4[i] = o;
    }
}

// ---------------- tf32 tensor-core GEMM for the four layer-2 projections ----------------
// C_z[M,N] = A[M,K] @ B_z[K,N] + bias_z, z = blockIdx.z in {q,k,v,s}.
// BM=128, BN=128, BK=32, 256 threads (8 warps as 2x4), mma.sync m16n8k8 tf32.
__device__ __forceinline__ float f2tf32(float x) {
    uint32_t r;
    asm("cvt.rna.tf32.f32 %0, %1;" : "=r"(r) : "f"(x));
    return __uint_as_float(r);
}

__global__ void __launch_bounds__(256, 2) gemm4_tf32_kernel(
    const float* __restrict__ A,
    const float* __restrict__ B0, const float* __restrict__ B1,
    const float* __restrict__ B2, const float* __restrict__ B3,
    const float* __restrict__ c0, const float* __restrict__ c1,
    const float* __restrict__ c2, const float* __restrict__ c3,
    float* C0, float* C1, float* C2, float* C3,
    int M, int N, int K)
{
    constexpr int BM = 128, BN = 128, BK = 32;
    __shared__ float As[BM][BK+4];    // [m][k], pad 36 -> frag banks (4m+k)%32 unique
    __shared__ float Bs[BK][BN+8];    // [k][n], pad 136 -> frag banks (8k+n)%32 unique

    int z = blockIdx.z;
    const float* Bw   = (z==0) ? B0 : (z==1) ? B1 : (z==2) ? B2 : B3;
    const float* bias = (z==0) ? c0 : (z==1) ? c1 : (z==2) ? c2 : c3;
    float*       C    = (z==0) ? C0 : (z==1) ? C1 : (z==2) ? C2 : C3;

    int tid  = threadIdx.x;
    int lane = tid & 31, wid = tid >> 5;
    int wm = wid >> 2, wn = wid & 3;          // 2 x 4 warp grid
    int m0 = blockIdx.x * BM, n0 = blockIdx.y * BN;
    int row = lane >> 2, col = lane & 3;

    float acc[4][4][4];
    #pragma unroll
    for (int a = 0; a < 4; ++a)
        #pragma unroll
        for (int b = 0; b < 4; ++b)
            #pragma unroll
            for (int c = 0; c < 4; ++c) acc[a][b][c] = 0.f;

    for (int kt = 0; kt < K; kt += BK) {
        // A tile: 128x32 = 1024 float4 loads across 256 threads
        #pragma unroll
        for (int i = 0; i < 4; ++i) {
            int idx = tid + i*256;
            int m = idx >> 3, k4 = (idx & 7) * 4;
            float4 v = make_float4(0.f,0.f,0.f,0.f);
            if (m0 + m < M)
                v = __ldg((const float4*)&A[(size_t)(m0+m)*K + kt + k4]);
            v.x = f2tf32(v.x); v.y = f2tf32(v.y);
            v.z = f2tf32(v.z); v.w = f2tf32(v.w);
            *(float4*)&As[m][k4] = v;
        }
        // B tile: 32x128 = 1024 float4 loads
        #pragma unroll
        for (int i = 0; i < 4; ++i) {
            int idx = tid + i*256;
            int k = idx >> 5, n4 = (idx & 31) * 4;
            float4 v = __ldg((const float4*)&Bw[(size_t)(kt+k)*N + n0 + n4]);
            v.x = f2tf32(v.x); v.y = f2tf32(v.y);
            v.z = f2tf32(v.z); v.w = f2tf32(v.w);
            *(float4*)&Bs[k][n4] = v;
        }
        __syncthreads();

        #pragma unroll
        for (int kc = 0; kc < 4; ++kc) {
            int kb = kc * 8;
            uint32_t af[4][4], bf[4][2];
            #pragma unroll
            for (int mt = 0; mt < 4; ++mt) {
                int mb = wm*64 + mt*16;
                af[mt][0] = __float_as_uint(As[mb+row  ][kb+col  ]);
                af[mt][1] = __float_as_uint(As[mb+row+8][kb+col  ]);
                af[mt][2] = __float_as_uint(As[mb+row  ][kb+col+4]);
                af[mt][3] = __float_as_uint(As[mb+row+8][kb+col+4]);
            }
            #pragma unroll
            for (int nt = 0; nt < 4; ++nt) {
                int nb = wn*32 + nt*8;
                bf[nt][0] = __float_as_uint(Bs[kb+col  ][nb+row]);
                bf[nt][1] = __float_as_uint(Bs[kb+col+4][nb+row]);
            }
            #pragma unroll
            for (int mt = 0; mt < 4; ++mt)
                #pragma unroll
                for (int nt = 0; nt < 4; ++nt) {
                    asm volatile(
                        "mma.sync.aligned.m16n8k8.row.col.f32.tf32.tf32.f32 "
                        "{%0,%1,%2,%3}, {%4,%5,%6,%7}, {%8,%9}, {%0,%1,%2,%3};"
                        : "+f"(acc[mt][nt][0]), "+f"(acc[mt][nt][1]),
                          "+f"(acc[mt][nt][2]), "+f"(acc[mt][nt][3])
                        : "r"(af[mt][0]), "r"(af[mt][1]), "r"(af[mt][2]), "r"(af[mt][3]),
                          "r"(bf[nt][0]), "r"(bf[nt][1]));
                }
        }
        __syncthreads();
    }

    // epilogue: c0,c1 -> (row, col*2 + {0,1}); c2,c3 -> (row+8, same)
    #pragma unroll
    for (int mt = 0; mt < 4; ++mt) {
        int r0 = m0 + wm*64 + mt*16 + row;
        #pragma unroll
        for (int nt = 0; nt < 4; ++nt) {
            int c = n0 + wn*32 + nt*8 + col*2;
            float bv0 = __ldg(&bias[c]), bv1 = __ldg(&bias[c+1]);
            if (r0 < M) {
                float2 o = make_float2(acc[mt][nt][0] + bv0, acc[mt][nt][1] + bv1);
                *(float2*)&C[(size_t)r0*N + c] = o;
            }
            if (r0 + 8 < M) {
                float2 o = make_float2(acc[mt][nt][2] + bv0, acc[mt][nt][3] + bv1);
                *(float2*)&C[(size_t)(r0+8)*N + c] = o;
            }
        }
    }
}

// ---------------- fp32 tiled GEMM (kept for small tail GEMMs) ----------------
__global__ void __launch_bounds__(256) gemm_kernel(
    const float* __restrict__ A, const float* __restrict__ Bm,
    const float* __restrict__ bias, float* __restrict__ C,
    int M, int N, int K, int ldc, int coff)
{
    __shared__ float As[16][128+4];
    __shared__ float Bs[16][64+4];
    int tid = threadIdx.x;
    int tx = tid & 15, ty = tid >> 4;
    int m0 = blockIdx.x * 128;
    int n0 = blockIdx.y * 64;
    float acc[8][4] = {};

    for (int k0 = 0; k0 < K; k0 += 16) {
        #pragma unroll
        for (int it = 0; it < 2; ++it) {
            int f = tid + it*256;
            int row = f >> 2;
            int c4 = (f & 3) * 4;
            float4 val = make_float4(0.f,0.f,0.f,0.f);
            if (m0 + row < M)
                val = __ldg((const float4*)&A[(size_t)(m0+row)*K + k0 + c4]);
            As[c4+0][row] = val.x; As[c4+1][row] = val.y;
            As[c4+2][row] = val.z; As[c4+3][row] = val.w;
        }
        {
            int r  = tid >> 4;
            int c4 = (tid & 15) * 4;
            float4 val = __ldg((const float4*)&Bm[(size_t)(k0+r)*N + n0 + c4]);
            *(float4*)&Bs[r][c4] = val;
        }
        __syncthreads();
        #pragma unroll
        for (int kk = 0; kk < 16; ++kk) {
            float a[8], b[4];
            *(float4*)&a[0] = *(const float4*)&As[kk][ty*8];
            *(float4*)&a[4] = *(const float4*)&As[kk][ty*8+4];
            *(float4*)&b[0] = *(const float4*)&Bs[kk][tx*4];
            #pragma unroll
            for (int i = 0; i < 8; ++i)
                #pragma unroll
                for (int j = 0; j < 4; ++j)
                    acc[i][j] = fmaf(a[i], b[j], acc[i][j]);
        }
        __syncthreads();
    }
    #pragma unroll
    for (int i = 0; i < 8; ++i) {
        int row = m0 + ty*8 + i;
        if (row < M) {
            #pragma unroll
            for (int j = 0; j < 4; ++j) {
                int col = n0 + tx*4 + j;
                C[(size_t)row*ldc + coff + col] = acc[i][j] + __ldg(&bias[col]);
            }
        }
    }
}

// ---------------- mean pool over 20 nodes per graph -> concat[:, :1024] ----------------
__global__ void pool_kernel() {
    int c = blockIdx.y*blockDim.x + threadIdx.x;   // 0..1023
    int b = blockIdx.x;
    float sum = 0.f;
    #pragma unroll
    for (int i = 0; i < NPG; ++i)
        sum += g_h2[(size_t)(b*NPG + i)*1024 + c];
    g_concat[b*1280 + c] = sum * (1.f/NPG);
}

// ---------------- launch ----------------
extern "C" void kernel_launch(void* const* d_in, const int* in_sizes, int n_in,
                              void* d_out, int out_size)
{
    const float* x    = (const float*)d_in[0];
    const int*   ei   = (const int*)  d_in[1];
    const float* ea   = (const float*)d_in[2];
    const float* fpb  = (const float*)d_in[4];
    const float *Wq1=(const float*)d_in[5],  *bq1=(const float*)d_in[6];
    const float *Wk1=(const float*)d_in[7],  *bk1=(const float*)d_in[8];
    const float *Wv1=(const float*)d_in[9],  *bv1=(const float*)d_in[10];
    const float *We1=(const float*)d_in[11];
    const float *Ws1=(const float*)d_in[12], *bs1=(const float*)d_in[13];
    const float *Wq2=(const float*)d_in[14], *bq2=(const float*)d_in[15];
    const float *Wk2=(const float*)d_in[16], *bk2=(const float*)d_in[17];
    const float *Wv2=(const float*)d_in[18], *bv2=(const float*)d_in[19];
    const float *We2=(const float*)d_in[20];
    const float *Ws2=(const float*)d_in[21], *bs2=(const float*)d_in[22];
    const float *Wfp=(const float*)d_in[23], *bfp=(const float*)d_in[24];
    const float *Wfin=(const float*)d_in[25],*bfin=(const float*)d_in[26];

    const int* srcArr = ei;
    const int* dstArr = ei + EE;

    float *q1,*k1,*v1,*s1,*h1,*q2,*k2,*v2,*s2,*h2,*cc;
    cudaGetSymbolAddress((void**)&q1, g_q1);
    cudaGetSymbolAddress((void**)&k1, g_k1);
    cudaGetSymbolAddress((void**)&v1, g_v1);
    cudaGetSymbolAddress((void**)&s1, g_s1);
    cudaGetSymbolAddress((void**)&h1, g_h1);
    cudaGetSymbolAddress((void**)&q2, g_q2);
    cudaGetSymbolAddress((void**)&k2, g_k2);
    cudaGetSymbolAddress((void**)&v2, g_v2);
    cudaGetSymbolAddress((void**)&s2, g_s2);
    cudaGetSymbolAddress((void**)&h2, g_h2);
    cudaGetSymbolAddress((void**)&cc, g_concat);

    // CSR build
    zero_deg_kernel<<<(NN+255)/256, 256>>>();
    hist_kernel<<<(EE+255)/256, 256>>>(dstArr);
    scan_kernel<<<1, 1024>>>();
    scatter_kernel<<<(EE+255)/256, 256>>>(dstArr);
    sort_kernel<<<(NN+255)/256, 256>>>();

    // layer 1
    proj1_kernel<<<(NN*32+255)/256, 256>>>(x, Wq1,bq1, Wk1,bk1, Wv1,bv1, Ws1,bs1);
    attn_kernel<512,4,true><<<(NN*32+255)/256, 256>>>(q1,k1,v1,s1, ea, We1, srcArr, h1);

    // layer 2 projections: one fused tf32 tensor-core launch for all four GEMMs
    {
        dim3 grid((NN+127)/128, 1024/128, 4);
        gemm4_tf32_kernel<<<grid, 256>>>(h1,
            Wq2, Wk2, Wv2, Ws2,
            bq2, bk2, bv2, bs2,
            q2, k2, v2, s2,
            NN, 1024, 512);
    }

    attn_kernel<1024,4,false><<<(NN*32+255)/256, 256>>>(q2,k2,v2,s2, ea, We2, srcArr, h2);

    // pooling + fingerprint + final (small; stay fp32 for accuracy headroom)
    pool_kernel<<<dim3(BB, 4), 256>>>();
    gemm_kernel<<<dim3((BB+127)/128, 256/64), 256>>>(fpb, Wfp, bfp, cc, BB, 256, 2048, 1280, 1024);
    gemm_kernel<<<dim3((BB+127)/128, 1024/64), 256>>>(cc, Wfin, bfin, (float*)d_out, BB, 1024, 1280, 1024, 0);
}